// round 4
// baseline (speedup 1.0000x reference)
#include <cuda_runtime.h>
#include <cstdint>

#define NQ 2048
#define NT 5
#define NTHREADS 256
#define NCAND 3125   // 5^5

static __device__ __forceinline__ unsigned long long umin64(unsigned long long a,
                                                            unsigned long long b) {
    return a < b ? a : b;
}

__global__ __launch_bounds__(NTHREADS, 1)
void hungarian_match_kernel(const float* __restrict__ pred_regs,   // [32, 2048, 3]
                            const float* __restrict__ tgt,         // [160, 3]
                            float* __restrict__ out,               // [2, 32, 5] as f32
                            int pr_count,
                            int tg_count,
                            int out_count)
{
    __shared__ float cost_sm[NT][NQ];        // 40 KB
    __shared__ float tg[NT][3];
    __shared__ int   sel_idx[NT][NT];
    __shared__ float sel_val[NT][NT];
    __shared__ unsigned long long red[NTHREADS / 32];

    const int b    = blockIdx.x;
    const int tid  = threadIdx.x;
    const int w    = tid >> 5;
    const int lane = tid & 31;

    // ---- load this batch's 5 targets (15 floats), bounds-guarded ----
    if (tid < NT * 3) {
        int gi = b * NT * 3 + tid;
        ((float*)tg)[tid] = (gi < tg_count) ? tgt[gi] : 0.0f;
    }
    __syncthreads();

    // ---- cost matrix: C[t][q] = |d0|+|d1|+|d2| + 1.0, bit-exact XLA order ----
    const float* pr = pred_regs + (size_t)b * NQ * 3;
    const int pr_base = b * NQ * 3;
    #pragma unroll
    for (int i = 0; i < NQ / NTHREADS; i++) {
        int q = tid + i * NTHREADS;
        bool ok = (pr_base + q * 3 + 2) < pr_count;
        float p0 = ok ? pr[q * 3 + 0] : 0.0f;
        float p1 = ok ? pr[q * 3 + 1] : 0.0f;
        float p2 = ok ? pr[q * 3 + 2] : 0.0f;
        #pragma unroll
        for (int t = 0; t < NT; t++) {
            float a0 = fabsf(__fsub_rn(p0, tg[t][0]));
            float a1 = fabsf(__fsub_rn(p1, tg[t][1]));
            float a2 = fabsf(__fsub_rn(p2, tg[t][2]));
            float c  = __fadd_rn(__fadd_rn(__fadd_rn(a0, a1), a2), 1.0f);
            cost_sm[t][q] = c;
        }
    }
    __syncthreads();

    // ---- per-target top-5 smallest (value,index), ascending, ties -> lower q ----
    // key = float_bits(cost)<<32 | q  (costs >= 1 > 0 so uint order == float order;
    // embedded index reproduces jax.lax.top_k's stable tie-break)
    if (w < NT) {
        const int t = w;
        int picked[NT];
        #pragma unroll
        for (int k = 0; k < NT; k++) {
            unsigned long long best = ~0ULL;
            #pragma unroll 4
            for (int i = 0; i < NQ / 32; i++) {
                int q = lane + i * 32;
                bool skip = false;
                #pragma unroll
                for (int j = 0; j < NT; j++)
                    if (j < k) skip |= (q == picked[j]);
                if (!skip) {
                    unsigned long long key =
                        ((unsigned long long)__float_as_uint(cost_sm[t][q]) << 32) |
                        (unsigned int)q;
                    best = umin64(best, key);
                }
            }
            #pragma unroll
            for (int s = 16; s > 0; s >>= 1)
                best = umin64(best, __shfl_xor_sync(0xffffffffu, best, s));
            picked[k] = (int)(unsigned int)best;
            if (lane == 0) {
                sel_idx[t][k] = picked[k];
                sel_val[t][k] = __uint_as_float((unsigned int)(best >> 32));
            }
        }
    }
    __syncthreads();

    // ---- enumerate 3125 tuples; argmin of f32 sum, first-occurrence tie-break ----
    unsigned long long best = ~0ULL;
    for (int n = tid; n < NCAND; n += NTHREADS) {
        int r  = n;
        int d0 = r / 625;  r -= d0 * 625;
        int d1 = r / 125;  r -= d1 * 125;
        int d2 = r / 25;   r -= d2 * 25;
        int d3 = r / 5;
        int d4 = r - d3 * 5;
        int q0 = sel_idx[0][d0], q1 = sel_idx[1][d1], q2 = sel_idx[2][d2],
            q3 = sel_idx[3][d3], q4 = sel_idx[4][d4];
        bool valid = (q0 != q1) && (q0 != q2) && (q0 != q3) && (q0 != q4) &&
                     (q1 != q2) && (q1 != q3) && (q1 != q4) &&
                     (q2 != q3) && (q2 != q4) && (q3 != q4);
        if (valid) {
            float tot = __fadd_rn(
                            __fadd_rn(
                                __fadd_rn(
                                    __fadd_rn(sel_val[0][d0], sel_val[1][d1]),
                                    sel_val[2][d2]),
                                sel_val[3][d3]),
                            sel_val[4][d4]);
            unsigned long long key =
                ((unsigned long long)__float_as_uint(tot) << 32) | (unsigned int)n;
            best = umin64(best, key);
        }
    }
    #pragma unroll
    for (int s = 16; s > 0; s >>= 1)
        best = umin64(best, __shfl_xor_sync(0xffffffffu, best, s));
    if (lane == 0) red[w] = best;
    __syncthreads();

    // ---- thread 0: decode winner, sort (rows, cols), write output as FLOAT ----
    if (tid == 0) {
        unsigned long long bb = red[0];
        #pragma unroll
        for (int i = 1; i < NTHREADS / 32; i++) bb = umin64(bb, red[i]);
        int n = (int)(unsigned int)bb;
        int d[NT];
        d[0] = n / 625; n %= 625;
        d[1] = n / 125; n %= 125;
        d[2] = n / 25;  n %= 25;
        d[3] = n / 5;
        d[4] = n % 5;
        int rows[NT], cols[NT];
        #pragma unroll
        for (int j = 0; j < NT; j++) { rows[j] = sel_idx[j][d[j]]; cols[j] = j; }
        // insertion sort by rows (rows distinct; stable sort => cols = argsort)
        #pragma unroll
        for (int i = 1; i < NT; i++) {
            int rv = rows[i], cv = cols[i], j = i - 1;
            while (j >= 0 && rows[j] > rv) {
                rows[j + 1] = rows[j]; cols[j + 1] = cols[j]; j--;
            }
            rows[j + 1] = rv; cols[j + 1] = cv;
        }
        #pragma unroll
        for (int j = 0; j < NT; j++) {
            int i0 = b * NT + j;              // output 0: rows  [32,5]
            int i1 = 32 * NT + b * NT + j;    // output 1: cols  [32,5]
            if (i0 < out_count) out[i0] = (float)rows[j];
            if (i1 < out_count) out[i1] = (float)cols[j];
        }
    }
}

extern "C" void kernel_launch(void* const* d_in, const int* in_sizes, int n_in,
                              void* d_out, int out_size) {
    // Expected inputs (any order):
    //   pred_logits    : 65536  f32  (unused)
    //   pred_regs      : 196608 f32  [32,2048,3]
    //   labels         : 160    i32  (unused)
    //   tgt_regression : 480    f32  [160,3]
    // Bind by size, accepting element counts or byte counts.
    int pr_i = -1, tg_i = -1;
    int pr_count = 196608, tg_count = 480;
    int max_i = 0;
    for (int i = 0; i < n_in; i++) {
        if (in_sizes[i] == 196608 || in_sizes[i] == 786432) pr_i = i;
        if (in_sizes[i] == 480    || in_sizes[i] == 1920)   tg_i = i;
        if (in_sizes[i] > in_sizes[max_i]) max_i = i;
    }
    if (pr_i < 0) pr_i = max_i;
    if (tg_i < 0) tg_i = (n_in > 3) ? 3 : n_in - 1;
    if (in_sizes[pr_i] == 786432) pr_count = 196608;
    else if (in_sizes[pr_i] < 196608) pr_count = in_sizes[pr_i];
    if (in_sizes[tg_i] == 1920) tg_count = 480;
    else if (in_sizes[tg_i] < 480) tg_count = in_sizes[tg_i];

    const float* pred_regs = (const float*)d_in[pr_i];
    const float* tgt       = (const float*)d_in[tg_i];
    float* out = (float*)d_out;
    hungarian_match_kernel<<<32, NTHREADS>>>(pred_regs, tgt, out,
                                             pr_count, tg_count, out_size);
}

// round 5
// speedup vs baseline: 1.0172x; 1.0172x over previous
#include <cuda_runtime.h>
#include <cstdint>

#define NQ 2048
#define NT 5
#define NTHREADS 256
#define NCAND 3125   // 5^5

static __device__ __forceinline__ unsigned long long umin64(unsigned long long a,
                                                            unsigned long long b) {
    return a < b ? a : b;
}
static __device__ __forceinline__ unsigned long long umax64(unsigned long long a,
                                                            unsigned long long b) {
    return a > b ? a : b;
}

// compare-exchange: a <- min, b <- max
#define CE(a, b) { unsigned long long _lo = umin64(a, b); b = umax64(a, b); a = _lo; }

__global__ __launch_bounds__(NTHREADS, 1)
void hungarian_match_kernel(const float* __restrict__ pred_regs,   // [32, 2048, 3]
                            const float* __restrict__ tgt,         // [160, 3]
                            float* __restrict__ out)               // [2, 32, 5] f32
{
    __shared__ float4 p4_sm[NQ];             // 32 KB: (x, y, z, pad)
    __shared__ float  tg_sm[NT * 3];
    __shared__ int    sel_idx[NT][NT];
    __shared__ float  sel_val[NT][NT];
    __shared__ unsigned long long red[NTHREADS / 32];

    const int b    = blockIdx.x;
    const int tid  = threadIdx.x;
    const int w    = tid >> 5;
    const int lane = tid & 31;

    // ---- stage targets + this batch's pred_regs into shared ----
    if (tid < NT * 3) tg_sm[tid] = tgt[b * NT * 3 + tid];

    const float* pr = pred_regs + (size_t)b * NQ * 3;
    #pragma unroll
    for (int i = 0; i < NQ / NTHREADS; i++) {
        int q = tid + i * NTHREADS;
        float p0 = pr[q * 3 + 0];
        float p1 = pr[q * 3 + 1];
        float p2 = pr[q * 3 + 2];
        p4_sm[q] = make_float4(p0, p1, p2, 0.0f);
    }
    __syncthreads();

    // ---- warps 0..4: single-pass top-5 (ascending) for target t = w ----
    // key = float_bits(cost)<<32 | q. costs >= 1 > 0 so uint order == float
    // order; embedded q reproduces jax.lax.top_k's stable tie-break.
    if (w < NT) {
        const int t = w;
        const float t0f = tg_sm[t * 3 + 0];
        const float t1f = tg_sm[t * 3 + 1];
        const float t2f = tg_sm[t * 3 + 2];

        unsigned long long m0 = ~0ULL, m1 = ~0ULL, m2 = ~0ULL,
                           m3 = ~0ULL, m4 = ~0ULL;

        #pragma unroll 4
        for (int i = 0; i < NQ / 32; i++) {
            int q = lane + i * 32;
            float4 p = p4_sm[q];
            float a0 = fabsf(__fsub_rn(p.x, t0f));
            float a1 = fabsf(__fsub_rn(p.y, t1f));
            float a2 = fabsf(__fsub_rn(p.z, t2f));
            float c  = __fadd_rn(__fadd_rn(__fadd_rn(a0, a1), a2), 1.0f);
            unsigned long long key =
                ((unsigned long long)__float_as_uint(c) << 32) | (unsigned int)q;
            if (key < m4) {              // rarely taken after warm-up
                m4 = key;
                unsigned long long tmp;
                if (m4 < m3) { tmp = m3; m3 = m4; m4 = tmp; }
                if (m3 < m2) { tmp = m2; m2 = m3; m3 = tmp; }
                if (m2 < m1) { tmp = m1; m1 = m2; m2 = tmp; }
                if (m1 < m0) { tmp = m0; m0 = m1; m1 = tmp; }
            }
        }

        // ---- warp merge: 5 bitonic levels; each keeps the 5 smallest ----
        #pragma unroll
        for (int off = 16; off > 0; off >>= 1) {
            unsigned long long o0 = __shfl_xor_sync(0xffffffffu, m0, off);
            unsigned long long o1 = __shfl_xor_sync(0xffffffffu, m1, off);
            unsigned long long o2 = __shfl_xor_sync(0xffffffffu, m2, off);
            unsigned long long o3 = __shfl_xor_sync(0xffffffffu, m3, off);
            unsigned long long o4 = __shfl_xor_sync(0xffffffffu, m4, off);
            // [m0..m4, o4..o0] is bitonic; lower half = 5 smallest
            unsigned long long s0 = umin64(m0, o4);
            unsigned long long s1 = umin64(m1, o3);
            unsigned long long s2 = umin64(m2, o2);
            unsigned long long s3 = umin64(m3, o1);
            unsigned long long s4 = umin64(m4, o0);
            // sort the (bitonic) 5-list ascending: Knuth 9-CE network
            CE(s0, s1); CE(s3, s4); CE(s2, s4); CE(s2, s3); CE(s0, s3);
            CE(s0, s2); CE(s1, s4); CE(s1, s3); CE(s1, s2);
            m0 = s0; m1 = s1; m2 = s2; m3 = s3; m4 = s4;
        }

        if (lane == 0) {
            sel_idx[t][0] = (int)(unsigned int)m0;
            sel_idx[t][1] = (int)(unsigned int)m1;
            sel_idx[t][2] = (int)(unsigned int)m2;
            sel_idx[t][3] = (int)(unsigned int)m3;
            sel_idx[t][4] = (int)(unsigned int)m4;
            sel_val[t][0] = __uint_as_float((unsigned int)(m0 >> 32));
            sel_val[t][1] = __uint_as_float((unsigned int)(m1 >> 32));
            sel_val[t][2] = __uint_as_float((unsigned int)(m2 >> 32));
            sel_val[t][3] = __uint_as_float((unsigned int)(m3 >> 32));
            sel_val[t][4] = __uint_as_float((unsigned int)(m4 >> 32));
        }
    }
    __syncthreads();

    // ---- enumerate 3125 tuples; argmin of f32 sum, first-occurrence ties ----
    unsigned long long best = ~0ULL;
    for (int n = tid; n < NCAND; n += NTHREADS) {
        int r  = n;
        int d0 = r / 625;  r -= d0 * 625;
        int d1 = r / 125;  r -= d1 * 125;
        int d2 = r / 25;   r -= d2 * 25;
        int d3 = r / 5;
        int d4 = r - d3 * 5;
        int q0 = sel_idx[0][d0], q1 = sel_idx[1][d1], q2 = sel_idx[2][d2],
            q3 = sel_idx[3][d3], q4 = sel_idx[4][d4];
        bool valid = (q0 != q1) && (q0 != q2) && (q0 != q3) && (q0 != q4) &&
                     (q1 != q2) && (q1 != q3) && (q1 != q4) &&
                     (q2 != q3) && (q2 != q4) && (q3 != q4);
        if (valid) {
            float tot = __fadd_rn(
                            __fadd_rn(
                                __fadd_rn(
                                    __fadd_rn(sel_val[0][d0], sel_val[1][d1]),
                                    sel_val[2][d2]),
                                sel_val[3][d3]),
                            sel_val[4][d4]);
            unsigned long long key =
                ((unsigned long long)__float_as_uint(tot) << 32) | (unsigned int)n;
            best = umin64(best, key);
        }
    }
    #pragma unroll
    for (int s = 16; s > 0; s >>= 1)
        best = umin64(best, __shfl_xor_sync(0xffffffffu, best, s));
    if (lane == 0) red[w] = best;
    __syncthreads();

    // ---- thread 0: decode winner, sort (rows, cols), write output as f32 ----
    if (tid == 0) {
        unsigned long long bb = red[0];
        #pragma unroll
        for (int i = 1; i < NTHREADS / 32; i++) bb = umin64(bb, red[i]);
        int n = (int)(unsigned int)bb;
        int d[NT];
        d[0] = n / 625; n %= 625;
        d[1] = n / 125; n %= 125;
        d[2] = n / 25;  n %= 25;
        d[3] = n / 5;
        d[4] = n % 5;
        int rows[NT], cols[NT];
        #pragma unroll
        for (int j = 0; j < NT; j++) { rows[j] = sel_idx[j][d[j]]; cols[j] = j; }
        // insertion sort by rows (rows distinct; stable sort => cols = argsort)
        #pragma unroll
        for (int i = 1; i < NT; i++) {
            int rv = rows[i], cv = cols[i], j = i - 1;
            while (j >= 0 && rows[j] > rv) {
                rows[j + 1] = rows[j]; cols[j + 1] = cols[j]; j--;
            }
            rows[j + 1] = rv; cols[j + 1] = cv;
        }
        #pragma unroll
        for (int j = 0; j < NT; j++) {
            out[b * NT + j]           = (float)rows[j];   // output 0: rows [32,5]
            out[32 * NT + b * NT + j] = (float)cols[j];   // output 1: cols [32,5]
        }
    }
}

extern "C" void kernel_launch(void* const* d_in, const int* in_sizes, int n_in,
                              void* d_out, int out_size) {
    // Bind by size (confirmed working): pred_regs = 196608 f32, tgt = 480 f32.
    int pr_i = -1, tg_i = -1, max_i = 0;
    for (int i = 0; i < n_in; i++) {
        if (in_sizes[i] == 196608 || in_sizes[i] == 786432) pr_i = i;
        if (in_sizes[i] == 480    || in_sizes[i] == 1920)   tg_i = i;
        if (in_sizes[i] > in_sizes[max_i]) max_i = i;
    }
    if (pr_i < 0) pr_i = max_i;
    if (tg_i < 0) tg_i = (n_in > 3) ? 3 : n_in - 1;

    const float* pred_regs = (const float*)d_in[pr_i];
    const float* tgt       = (const float*)d_in[tg_i];
    float* out = (float*)d_out;
    hungarian_match_kernel<<<32, NTHREADS>>>(pred_regs, tgt, out);
}